// round 15
// baseline (speedup 1.0000x reference)
#include <cuda_runtime.h>
#include <cuda_fp16.h>
#include <math.h>
#include <stdint.h>

#define NB 8
#define SEQ 256
#define DIM 512
#define NH 8
#define HDIM 64
#define NLAYER 4
#define ROWS (NB*SEQ)
#define RD (ROWS*DIM)
#define NEGV -1e30f

typedef __half hf;
typedef __half2 hf2;

// ---------------- static scratch ----------------
__device__ float g_av [2*RD];
__device__ float g_vo [RD];
__device__ float g_qk [2*RD];
__device__ float g_pt [2*RD];
__device__ float g_sim[NB*SEQ*SEQ];

__device__ hf m_aud[RD];
__device__ hf m_vid[ROWS*256];
__device__ hf m_av [3*RD];
__device__ hf m_qk [2*RD];
__device__ hf m_qkv[6*RD];
__device__ hf m_ctx[2*RD];
__device__ hf m_h  [2*ROWS*2048];
__device__ hf m_sc [2*NB*NH*SEQ*SEQ];
__device__ hf m_sim[NB*SEQ*SEQ];
__device__ hf m_cat[ROWS*1024];

// fp16 weights, NATIVE [K][N] layout
__device__ hf c_ap[512*512];
__device__ hf c_vp[256*512];
__device__ hf c_dtw[512*512];
__device__ hf c_ca[32*512*512];
__device__ hf c_sa[32*512*512];
__device__ hf c_f1[8*512*2048];
__device__ hf c_f2[8*2048*512];
__device__ hf c_o[1024*512];

// ---------------- PTX helpers ----------------
__device__ __forceinline__ uint32_t smem_u32(const void* p) {
    return (uint32_t)__cvta_generic_to_shared(p);
}
__device__ __forceinline__ void cp16(uint32_t so, const void* g) {
    asm volatile("cp.async.cg.shared.global [%0], [%1], 16;" :: "r"(so), "l"(g));
}
__device__ __forceinline__ void ldm4(uint32_t* r, uint32_t addr) {
    asm volatile("ldmatrix.sync.aligned.m8n8.x4.shared.b16 {%0,%1,%2,%3}, [%4];"
        : "=r"(r[0]), "=r"(r[1]), "=r"(r[2]), "=r"(r[3]) : "r"(addr));
}
__device__ __forceinline__ void ldm4t(uint32_t* r, uint32_t addr) {
    asm volatile("ldmatrix.sync.aligned.m8n8.x4.trans.shared.b16 {%0,%1,%2,%3}, [%4];"
        : "=r"(r[0]), "=r"(r[1]), "=r"(r[2]), "=r"(r[3]) : "r"(addr));
}
__device__ __forceinline__ void mma16816(float* d, const uint32_t* a, const uint32_t* b) {
    asm volatile(
        "mma.sync.aligned.m16n8k16.row.col.f32.f16.f16.f32 "
        "{%0,%1,%2,%3}, {%4,%5,%6,%7}, {%8,%9}, {%0,%1,%2,%3};"
        : "+f"(d[0]), "+f"(d[1]), "+f"(d[2]), "+f"(d[3])
        : "r"(a[0]), "r"(a[1]), "r"(a[2]), "r"(a[3]), "r"(b[0]), "r"(b[1]));
}

// ---------------- HMMA GEMM: C = epi(A@B), fp16 single-pass, fp32 accum ----------------
// NKS: number of 32-K sub-blocks per pipeline stage (commit granularity = stage).
template<int BM, int BN, int NWM, int NWN, bool TRB, bool FSM, int NST, int NKS>
__global__ void __launch_bounds__(NWM*NWN*32, (NWM*NWN*32 <= 128) ? 3 : 2)
mma_gemm(const hf* __restrict__ A_, const hf* __restrict__ B_,
         float* __restrict__ C,
         int K, int lda, int ldb, int ldc,
         long long sAo, long long sAi, long long sBo, long long sBi,
         long long sCo, long long sCi, int inner,
         float alpha, const float* __restrict__ bias, long long sBO, long long sBI,
         const float* __restrict__ bias2,
         const float* __restrict__ resid, float rscale, int beta, int act,
         hf* outh)
{
    constexpr int TH = NWM * NWN * 32;
    constexpr int WM = BM / NWM;
    constexpr int MF = WM / 16;
    constexpr int WN = BN / NWN;
    constexpr int NF = WN / 8;
    constexpr int ACH = BM * 4;
    constexpr int BCH = BN * 4;
    constexpr int CPR = BN / 8;
    constexpr int SUB = (BM + BN) * 64;   // one 32-K sub-block
    constexpr int STAGE = NKS * SUB;
    constexpr int CH = 32 * NKS;          // K-elems per stage

    extern __shared__ char smem[];
    uint32_t sb = smem_u32(smem);
    __shared__ float sred[FSM ? BM : 1][NWN];

    int z = blockIdx.z, zo = z / inner, zi = z - zo * inner;
    A_ += zo * sAo + zi * sAi;
    B_ += zo * sBo + zi * sBi;
    long long coff = zo * sCo + zi * sCi;
    if (C) C += coff;
    if (resid) resid += coff;
    if (outh) outh += coff;
    if (bias) bias += zo * sBO + zi * sBI;

    int tid = threadIdx.x, wid = tid >> 5, lane = tid & 31;
    int wm = wid % NWM, wn = wid / NWM;
    int row0 = blockIdx.y * BM, col0 = blockIdx.x * BN;

    auto loadStage = [&](int k0, int st) {
        uint32_t sbase0 = sb + st * STAGE;
#pragma unroll
        for (int q = 0; q < NKS; q++) {
            uint32_t sbase = sbase0 + q * SUB;
            int kq = k0 + q * 32;
#pragma unroll
            for (int idx = tid; idx < ACH; idx += TH) {
                int r = idx >> 2, c = idx & 3;
                int cs = c ^ ((r >> 1) & 3);
                uint32_t so = sbase + (uint32_t)(r * 4 + cs) * 16;
                long long g = (long long)(row0 + r) * lda + kq + c * 8;
                cp16(so, A_ + g);
            }
            if (!TRB) {
#pragma unroll
                for (int idx = tid; idx < BCH; idx += TH) {
                    int r = idx >> 2, c = idx & 3;
                    int cs = c ^ ((r >> 1) & 3);
                    uint32_t so = sbase + BM * 64 + (uint32_t)(r * 4 + cs) * 16;
                    long long g = (long long)(col0 + r) * ldb + kq + c * 8;
                    cp16(so, B_ + g);
                }
            } else {
#pragma unroll
                for (int idx = tid; idx < BCH; idx += TH) {
                    int r = idx / CPR, c = idx % CPR;
                    int cs = c ^ (r & 7);
                    uint32_t so = sbase + BM * 64 + (uint32_t)(r * CPR + cs) * 16;
                    long long g = (long long)(kq + r) * ldb + col0 + c * 8;
                    cp16(so, B_ + g);
                }
            }
        }
        asm volatile("cp.async.commit_group;");
    };

    float acc[MF][NF][4];
#pragma unroll
    for (int i = 0; i < MF; i++)
#pragma unroll
        for (int j = 0; j < NF; j++)
#pragma unroll
            for (int q = 0; q < 4; q++) acc[i][j][q] = 0.f;

    int nch = K / CH;
#pragma unroll
    for (int p = 0; p < NST - 1; p++)
        if (p < nch) loadStage(p * CH, p);

    for (int s = 0; s < nch; s++) {
        int rem = nch - 1 - s;
        if (NST == 2) {
            asm volatile("cp.async.wait_group 0;");
        } else if (NST == 3) {
            if (rem >= 1) { asm volatile("cp.async.wait_group 1;"); }
            else          { asm volatile("cp.async.wait_group 0;"); }
        } else {
            if (rem >= 2)      { asm volatile("cp.async.wait_group 2;"); }
            else if (rem == 1) { asm volatile("cp.async.wait_group 1;"); }
            else               { asm volatile("cp.async.wait_group 0;"); }
        }
        __syncthreads();
        if (s + NST - 1 < nch) loadStage((s + NST - 1) * CH, (s + NST - 1) % NST);
        uint32_t stg = sb + (s % NST) * STAGE;
#pragma unroll
        for (int ks = 0; ks < 2 * NKS; ks++) {
            uint32_t sbase = stg + (ks >> 1) * SUB;
            int kk = ks & 1;
            uint32_t ah[MF][4];
#pragma unroll
            for (int mf = 0; mf < MF; mf++) {
                int row = wm * WM + mf * 16 + (lane & 15);
                int c = kk * 2 + (lane >> 4);
                int cs = c ^ ((row >> 1) & 3);
                uint32_t ad = sbase + (uint32_t)(row * 4 + cs) * 16;
                ldm4(ah[mf], ad);
            }
            uint32_t bh[NF][2];
            if (!TRB) {
#pragma unroll
                for (int nf = 0; nf < NF; nf += 2) {
                    int rown = wn * WN + nf * 8 + (lane >> 4) * 8 + (lane & 7);
                    int c = kk * 2 + ((lane >> 3) & 1);
                    int cs = c ^ ((rown >> 1) & 3);
                    uint32_t bd = sbase + BM * 64 + (uint32_t)(rown * 4 + cs) * 16;
                    uint32_t t[4];
                    ldm4(t, bd);
                    bh[nf][0] = t[0]; bh[nf][1] = t[1]; bh[nf+1][0] = t[2]; bh[nf+1][1] = t[3];
                }
            } else {
#pragma unroll
                for (int nf = 0; nf < NF; nf += 2) {
                    int n0 = wn * WN + nf * 8;
                    int k = kk * 16 + (lane & 7) + ((lane >> 3) & 1) * 8;
                    int c = (n0 >> 3) + (lane >> 4);
                    int cs = c ^ (k & 7);
                    uint32_t bd = sbase + BM * 64 + (uint32_t)(k * CPR + cs) * 16;
                    uint32_t t[4];
                    ldm4t(t, bd);
                    bh[nf][0] = t[0]; bh[nf][1] = t[1]; bh[nf+1][0] = t[2]; bh[nf+1][1] = t[3];
                }
            }
#pragma unroll
            for (int mf = 0; mf < MF; mf++)
#pragma unroll
                for (int nf = 0; nf < NF; nf++)
                    mma16816(acc[mf][nf], ah[mf], bh[nf]);
        }
    }

    if (FSM) {
        __syncthreads();
        float rmax[MF][2], rsum[MF][2];
#pragma unroll
        for (int mf = 0; mf < MF; mf++)
#pragma unroll
            for (int h = 0; h < 2; h++) {
                float m = NEGV;
#pragma unroll
                for (int nf = 0; nf < NF; nf++) {
                    m = fmaxf(m, fmaxf(acc[mf][nf][h*2], acc[mf][nf][h*2+1]));
                }
                m = fmaxf(m, __shfl_xor_sync(0xffffffffu, m, 1));
                m = fmaxf(m, __shfl_xor_sync(0xffffffffu, m, 2));
                int rl = wm * WM + mf * 16 + (lane >> 2) + h * 8;
                if ((lane & 3) == 0) sred[rl][wn] = m;
                rmax[mf][h] = m;
            }
        __syncthreads();
#pragma unroll
        for (int mf = 0; mf < MF; mf++)
#pragma unroll
            for (int h = 0; h < 2; h++) {
                int rl = wm * WM + mf * 16 + (lane >> 2) + h * 8;
                float m = sred[rl][0];
#pragma unroll
                for (int w = 1; w < NWN; w++) m = fmaxf(m, sred[rl][w]);
                rmax[mf][h] = m;
            }
        __syncthreads();
#pragma unroll
        for (int mf = 0; mf < MF; mf++)
#pragma unroll
            for (int h = 0; h < 2; h++) {
                float ssum = 0.f;
#pragma unroll
                for (int nf = 0; nf < NF; nf++) {
                    float e0 = expf(acc[mf][nf][h*2]   * alpha - rmax[mf][h] * alpha);
                    float e1 = expf(acc[mf][nf][h*2+1] * alpha - rmax[mf][h] * alpha);
                    acc[mf][nf][h*2] = e0; acc[mf][nf][h*2+1] = e1;
                    ssum += e0 + e1;
                }
                ssum += __shfl_xor_sync(0xffffffffu, ssum, 1);
                ssum += __shfl_xor_sync(0xffffffffu, ssum, 2);
                int rl = wm * WM + mf * 16 + (lane >> 2) + h * 8;
                if ((lane & 3) == 0) sred[rl][wn] = ssum;
            }
        __syncthreads();
#pragma unroll
        for (int mf = 0; mf < MF; mf++)
#pragma unroll
            for (int h = 0; h < 2; h++) {
                int rl = wm * WM + mf * 16 + (lane >> 2) + h * 8;
                float t = 0.f;
#pragma unroll
                for (int w = 0; w < NWN; w++) t += sred[rl][w];
                rsum[mf][h] = 1.f / t;
            }
#pragma unroll
        for (int mf = 0; mf < MF; mf++) {
#pragma unroll
            for (int h = 0; h < 2; h++) {
                int r = row0 + wm * WM + mf * 16 + (lane >> 2) + h * 8;
#pragma unroll
                for (int nf = 0; nf < NF; nf++) {
                    int c = wn * WN + nf * 8 + (lane & 3) * 2;
                    long long off = (long long)r * ldc + c;
                    float v0 = acc[mf][nf][h*2]   * rsum[mf][h];
                    float v1 = acc[mf][nf][h*2+1] * rsum[mf][h];
                    *(hf2*)&outh[off] = hf2(__float2half_rn(v0), __float2half_rn(v1));
                }
            }
        }
        return;
    }

    auto epi2 = [&](int r, int c, float v0, float v1) {
        long long off = (long long)r * ldc + c;
        v0 *= alpha; v1 *= alpha;
        if (bias)  { float2 b2 = *(const float2*)&bias[c];  v0 += b2.x; v1 += b2.y; }
        if (bias2) { float2 b2 = *(const float2*)&bias2[c]; v0 += b2.x; v1 += b2.y; }
        if (beta)  { float2 c2 = *(const float2*)&C[off];   v0 += c2.x; v1 += c2.y; }
        if (resid) { float2 r2 = *(const float2*)&resid[off]; v0 += rscale * r2.x; v1 += rscale * r2.y; }
        if (act) {
            v0 = 0.5f * v0 * (1.f + erff(v0 * 0.70710678118654752f));
            v1 = 0.5f * v1 * (1.f + erff(v1 * 0.70710678118654752f));
        }
        if (C) *(float2*)&C[off] = make_float2(v0, v1);
        if (outh)
            *(hf2*)&outh[off] = hf2(__float2half_rn(v0), __float2half_rn(v1));
    };
#pragma unroll
    for (int mf = 0; mf < MF; mf++) {
        int r0 = row0 + wm * WM + mf * 16 + (lane >> 2);
#pragma unroll
        for (int nf = 0; nf < NF; nf++) {
            int c = col0 + wn * WN + nf * 8 + (lane & 3) * 2;
            epi2(r0,     c, acc[mf][nf][0], acc[mf][nf][1]);
            epi2(r0 + 8, c, acc[mf][nf][2], acc[mf][nf][3]);
        }
    }
}

// ---------------- mega convert ----------------
#define NSEG 10
struct CvtArgs {
    const float* src[NSEG];
    hf* dh[NSEG];
    long long cum[NSEG + 1];
};
__global__ void cvtall_k(CvtArgs a)
{
    long long i = ((long long)blockIdx.x * 256 + threadIdx.x) * 4;
    if (i >= a.cum[NSEG]) return;
    int s = 0;
#pragma unroll
    for (int q = 0; q < NSEG; q++) if (i >= a.cum[q + 1]) s = q + 1;
    long long o = i - a.cum[s];
    float4 v = *(const float4*)(a.src[s] + o);
    *(hf2*)(a.dh[s] + o)     = hf2(__float2half_rn(v.x), __float2half_rn(v.y));
    *(hf2*)(a.dh[s] + o + 2) = hf2(__float2half_rn(v.z), __float2half_rn(v.w));
}

// ---------------- softmax 256-wide -> fp16 (sim path only) ----------------
__global__ void softmax256_k(const float* __restrict__ x, hf* __restrict__ oh)
{
    __shared__ float red[8];
    __shared__ float bc[2];
    int t = threadIdx.x;
    const float* p = x + (long long)blockIdx.x * 256;
    float v = p[t];
    float m = v;
#pragma unroll
    for (int o = 16; o; o >>= 1) m = fmaxf(m, __shfl_xor_sync(0xffffffffu, m, o));
    if ((t & 31) == 0) red[t >> 5] = m;
    __syncthreads();
    if (t == 0) { float mm = red[0]; for (int i = 1; i < 8; i++) mm = fmaxf(mm, red[i]); bc[0] = mm; }
    __syncthreads();
    float e = expf(v - bc[0]);
    float s = e;
#pragma unroll
    for (int o = 16; o; o >>= 1) s += __shfl_xor_sync(0xffffffffu, s, o);
    if ((t & 31) == 0) red[t >> 5] = s;
    __syncthreads();
    if (t == 0) { float tt = 0.f; for (int i = 0; i < 8; i++) tt += red[i]; bc[1] = 1.f / tt; }
    __syncthreads();
    oh[(long long)blockIdx.x * 256 + t] = __float2half_rn(e * bc[1]);
}

// ---------------- LayerNorm 512 wide ----------------
__global__ void ln512_k(const float* __restrict__ x, const float* r, float* y,
                        const float* __restrict__ g1, const float* __restrict__ b1,
                        const float* g2, const float* b2,
                        hf* oh, int ldm, int moff0, int moff1, int rps)
{
    __shared__ float red[8];
    __shared__ float bc;
    long long row = blockIdx.x;
    int t = threadIdx.x;
    bool s2 = (g2 != nullptr) && (row >= rps);
    const float* g = s2 ? g2 : g1;
    const float* bb = s2 ? b2 : b1;
    const float* px = x + row * 512;
    float v0 = px[t], v1 = px[t + 256];
    if (r) { const float* pr = r + row * 512; v0 += pr[t]; v1 += pr[t + 256]; }
    float s = v0 + v1;
#pragma unroll
    for (int o = 16; o; o >>= 1) s += __shfl_xor_sync(0xffffffffu, s, o);
    if ((t & 31) == 0) red[t >> 5] = s;
    __syncthreads();
    if (t == 0) { float tt = 0.f; for (int i = 0; i < 8; i++) tt += red[i]; bc = tt * (1.f / 512.f); }
    __syncthreads();
    float mean = bc;
    float d0 = v0 - mean, d1 = v1 - mean;
    float q = d0 * d0 + d1 * d1;
#pragma unroll
    for (int o = 16; o; o >>= 1) q += __shfl_xor_sync(0xffffffffu, q, o);
    if ((t & 31) == 0) red[t >> 5] = q;
    __syncthreads();
    if (t == 0) { float tt = 0.f; for (int i = 0; i < 8; i++) tt += red[i]; bc = tt * (1.f / 512.f); }
    __syncthreads();
    float inv = rsqrtf(bc + 1e-5f);
    float y0 = d0 * inv * g[t]       + bb[t];
    float y1 = d1 * inv * g[t + 256] + bb[t + 256];
    float* py = y + row * 512;
    py[t] = y0;  py[t + 256] = y1;
    if (oh) {
        long long mo = s2 ? ((row - rps) * (long long)ldm + moff1)
                          : (row * (long long)ldm + moff0);
        oh[mo + t] = __float2half_rn(y0);
        oh[mo + t + 256] = __float2half_rn(y1);
    }
}

// ---------------- L2 normalize ----------------
__global__ void l2n_k(float* x, hf* oh)
{
    __shared__ float red[8];
    __shared__ float bc;
    long long row = blockIdx.x;
    int t = threadIdx.x;
    float* p = x + row * 512;
    float v0 = p[t], v1 = p[t + 256];
    float q = v0 * v0 + v1 * v1;
#pragma unroll
    for (int o = 16; o; o >>= 1) q += __shfl_xor_sync(0xffffffffu, q, o);
    if ((t & 31) == 0) red[t >> 5] = q;
    __syncthreads();
    if (t == 0) { float tt = 0.f; for (int i = 0; i < 8; i++) tt += red[i];
                  bc = 1.f / fmaxf(sqrtf(tt), 1e-12f); }
    __syncthreads();
    v0 *= bc; v1 *= bc;
    p[t] = v0; p[t + 256] = v1;
    oh[row * 512 + t] = __float2half_rn(v0);
    oh[row * 512 + t + 256] = __float2half_rn(v1);
}

// ---------------- DTW wavefront DP ----------------
__global__ void dtw_k(const float* __restrict__ sim, float* score)
{
    __shared__ float buf[3][SEQ + 1];
    int b = blockIdx.x;
    const float* S = sim + (long long)b * SEQ * SEQ;
    int t = threadIdx.x;
    float *dm2 = buf[0], *dm1 = buf[1], *dc = buf[2];
    if (t == 0) { buf[0][0] = 0.f; buf[1][0] = NEGV; buf[1][1] = NEGV; }
    __syncthreads();
    for (int td = 2; td <= 2 * SEQ; td++) {
        int i = t + 1;
        int j = td - i;
        float val = 0.f;
        bool active = (j >= 1 && j <= SEQ);
        if (active) {
            float dg = dm2[i - 1];
            float up = dm1[i - 1];
            float lf = dm1[i];
            val = S[(i - 1) * SEQ + (j - 1)] + fmaxf(dg, fmaxf(up, lf));
            dc[i] = val;
        }
        if (t == 0 && td <= SEQ) { dc[0] = NEGV; dc[td] = NEGV; }
        if (td == 2 * SEQ && i == SEQ) score[b] = val;
        __syncthreads();
        float* tmp = dm2; dm2 = dm1; dm1 = dc; dc = tmp;
    }
}

// ---------------- launch helpers ----------------
template<bool TRB>
static void tcgT(const hf* A, const hf* B,
                 float* C, int M, int N, int K, int lda, int ldb, int ldc,
                 long long sAo, long long sAi, long long sBo, long long sBi,
                 long long sCo, long long sCi, int inner, int batch,
                 float alpha, const float* bias, long long sBO, long long sBI,
                 const float* bias2,
                 const float* resid, float rs, int beta, int act,
                 hf* outh)
{
    static const int cand[3][2] = { {128,128}, {64,128}, {64,64} };
    int chosen = -1, best = -1;
    long long bestC = -1;
    for (int i = 0; i < 3; i++) {
        int bm = cand[i][0], bn = cand[i][1];
        if (M % bm || N % bn) continue;
        long long c = (long long)(M / bm) * (N / bn) * batch;
        if (c >= 240) { chosen = i; break; }
        if (c > bestC) { bestC = c; best = i; }
    }
    if (chosen < 0) chosen = best;
    if (chosen == 0) {
        constexpr int SM = 3 * 2 * (128 + 128) * 64;
        cudaFuncSetAttribute(mma_gemm<128,128,4,2,TRB,false,3,2>, cudaFuncAttributeMaxDynamicSharedMemorySize, SM);
        mma_gemm<128,128,4,2,TRB,false,3,2><<<dim3(N/128, M/128, batch), 256, SM>>>(
            A, B, C, K, lda, ldb, ldc, sAo, sAi, sBo, sBi, sCo, sCi, inner,
            alpha, bias, sBO, sBI, bias2, resid, rs, beta, act, outh);
    } else if (chosen == 1) {
        // workhorse: 64-K stages, 3-stage pipeline
        constexpr int SM = 3 * 2 * (64 + 128) * 64;
        cudaFuncSetAttribute(mma_gemm<64,128,2,2,TRB,false,3,2>, cudaFuncAttributeMaxDynamicSharedMemorySize, SM);
        mma_gemm<64,128,2,2,TRB,false,3,2><<<dim3(N/128, M/64, batch), 128, SM>>>(
            A, B, C, K, lda, ldb, ldc, sAo, sAi, sBo, sBi, sCo, sCi, inner,
            alpha, bias, sBO, sBI, bias2, resid, rs, beta, act, outh);
    } else {
        constexpr int SM = 3 * 2 * (64 + 64) * 64;
        cudaFuncSetAttribute(mma_gemm<64,64,2,2,TRB,false,3,2>, cudaFuncAttributeMaxDynamicSharedMemorySize, SM);
        mma_gemm<64,64,2,2,TRB,false,3,2><<<dim3(N/64, M/64, batch), 128, SM>>>(
            A, B, C, K, lda, ldb, ldc, sAo, sAi, sBo, sBi, sCo, sCi, inner,
            alpha, bias, sBO, sBI, bias2, resid, rs, beta, act, outh);
    }
}

// fused scores+softmax (K=64 -> single fully-prologue-loaded stage)
static void tcgS(const hf* A, const hf* B,
                 long long sAo, long long sAi, long long sBo, long long sBi,
                 long long sCo, long long sCi, int inner, int batch,
                 float alpha, hf* outh)
{
    constexpr int SM = 2 * 2 * (64 + 256) * 64;
    cudaFuncSetAttribute(mma_gemm<64,256,2,4,false,true,2,2>, cudaFuncAttributeMaxDynamicSharedMemorySize, SM);
    mma_gemm<64,256,2,4,false,true,2,2><<<dim3(1, SEQ/64, batch), 256, SM>>>(
        A, B, nullptr, HDIM, DIM, DIM, SEQ,
        sAo, sAi, sBo, sBi, sCo, sCi, inner,
        alpha, nullptr, 0, 0, nullptr, nullptr, 0.f, 0, 0, outh);
}

extern "C" void kernel_launch(void* const* d_in, const int* in_sizes, int n_in,
                              void* d_out, int out_size)
{
    const float* audio  = (const float*)d_in[0];
    const float* video  = (const float*)d_in[1];
    const float* ap_w   = (const float*)d_in[2];
    const float* ap_b   = (const float*)d_in[3];
    const float* vp_w   = (const float*)d_in[4];
    const float* vp_b   = (const float*)d_in[5];
    const float* dtw_w  = (const float*)d_in[6];
    const float* dtw_b  = (const float*)d_in[7];
    const float* mod_emb= (const float*)d_in[8];
    const float* ca_w   = (const float*)d_in[9];
    const float* ca_b   = (const float*)d_in[10];
    const float* sa_w   = (const float*)d_in[11];
    const float* sa_b   = (const float*)d_in[12];
    const float* ln_g   = (const float*)d_in[13];
    const float* ln_b   = (const float*)d_in[14];
    const float* ffn_w1 = (const float*)d_in[15];
    const float* ffn_b1 = (const float*)d_in[16];
    const float* ffn_w2 = (const float*)d_in[17];
    const float* ffn_b2 = (const float*)d_in[18];
    const float* out_w  = (const float*)d_in[19];
    const float* out_b  = (const float*)d_in[20];
    const float* fln_g  = (const float*)d_in[21];
    const float* fln_b  = (const float*)d_in[22];

    float *pav,*pvo,*pqk,*ppt,*psim;
    cudaGetSymbolAddress((void**)&pav, g_av);
    cudaGetSymbolAddress((void**)&pvo, g_vo);
    cudaGetSymbolAddress((void**)&pqk, g_qk);
    cudaGetSymbolAddress((void**)&ppt, g_pt);
    cudaGetSymbolAddress((void**)&psim,g_sim);

    hf *aud,*vid,*av,*qk,*qkv,*ctx,*hh,*sc,*sim,*cat;
    hf *apw,*vpw,*dtww,*caw,*saw,*f1w,*f2w,*oww;
    cudaGetSymbolAddress((void**)&aud, m_aud);
    cudaGetSymbolAddress((void**)&vid, m_vid);
    cudaGetSymbolAddress((void**)&av, m_av);
    cudaGetSymbolAddress((void**)&qk, m_qk);
    cudaGetSymbolAddress((void**)&qkv, m_qkv);
    cudaGetSymbolAddress((void**)&ctx, m_ctx);
    cudaGetSymbolAddress((void**)&hh, m_h);
    cudaGetSymbolAddress((void**)&sc, m_sc);
    cudaGetSymbolAddress((void**)&sim, m_sim);
    cudaGetSymbolAddress((void**)&cat, m_cat);
    cudaGetSymbolAddress((void**)&apw, c_ap);
    cudaGetSymbolAddress((void**)&vpw, c_vp);
    cudaGetSymbolAddress((void**)&dtww, c_dtw);
    cudaGetSymbolAddress((void**)&caw, c_ca);
    cudaGetSymbolAddress((void**)&saw, c_sa);
    cudaGetSymbolAddress((void**)&f1w, c_f1);
    cudaGetSymbolAddress((void**)&f2w, c_f2);
    cudaGetSymbolAddress((void**)&oww, c_o);

    float* out = (float*)d_out;
    float* out_score = out + (out_size - NB);

    const long long SD  = (long long)SEQ * DIM;
    const long long SS  = (long long)SEQ * SEQ;
    const long long W   = (long long)DIM * DIM;
    const long long Q2  = 2LL * RD;

    // ---- ONE convert launch ----
    {
        CvtArgs a;
        const float* srcs[NSEG] = { ap_w, vp_w, dtw_w, ca_w, sa_w, ffn_w1, ffn_w2, out_w, audio, video };
        hf* dhs[NSEG] = { apw, vpw, dtww, caw, saw, f1w, f2w, oww, aud, vid };
        long long ns[NSEG] = { 512*512, 256*512, 512*512, 32ll*512*512, 32ll*512*512,
                               8ll*512*2048, 8ll*2048*512, 1024*512, (long long)RD, (long long)ROWS*256 };
        long long cum = 0;
        for (int i = 0; i < NSEG; i++) {
            a.src[i] = srcs[i]; a.dh[i] = dhs[i];
            a.cum[i] = cum; cum += ns[i];
        }
        a.cum[NSEG] = cum;
        cvtall_k<<<(int)((cum / 4 + 255) / 256), 256>>>(a);
    }

    // ---- projections ----
    tcgT<true>(aud, apw, pav, ROWS, DIM, DIM, DIM, DIM, DIM,
               0,0,0,0,0,0, 1, 1, 1.f, ap_b, 0,0, mod_emb, nullptr, 0.f, 0, 0, av);
    tcgT<true>(vid, vpw, pvo, ROWS, DIM, 256, 256, DIM, DIM,
               0,0,0,0,0,0, 1, 1, 1.f, vp_b, 0,0, mod_emb + DIM, nullptr, 0.f, 0, 0, av + 2*RD);

    // ---- DTW ----
    tcgT<true>(av, dtww, pqk, ROWS, DIM, DIM, DIM, DIM, DIM,
               2*RD, 0, 0, 0, RD, 0, 1, 2,
               1.f, dtw_b, 0,0, nullptr, nullptr, 0.f, 0, 0, qk);
    l2n_k<<<2*ROWS, 256>>>(pqk, qk);
    tcgT<false>(qk, qk + RD, psim, SEQ, SEQ, DIM, DIM, DIM, SEQ,
                SD, 0, SD, 0, SS, 0, 1, NB,
                1.f, nullptr, 0,0, nullptr, nullptr, 0.f, 0, 0, nullptr);
    dtw_k<<<NB, 256>>>(psim, out_score);
    softmax256_k<<<NB*SEQ, 256>>>(psim, sim);
    tcgT<true>(sim, av + 2*RD, pav + RD, SEQ, DIM, SEQ, SEQ, DIM, DIM,
               SS, 0, SD, 0, SD, 0, 1, NB,
               0.5f, nullptr, 0,0, nullptr, pvo, 0.5f, 0, 0, av + RD);

    auto cross = [&](int s, const hf* Wh, const float* bb,
                     const float* lg, const float* lb) {
        long long so = (long long)s * RD;
        long long d  = (1 - 2 * s) * (long long)RD;
        tcgT<true>(av + so, Wh, nullptr, ROWS, DIM, DIM, DIM, DIM, DIM,
                   d, d, 2*W, W, 2*Q2, Q2, 2, 3,
                   1.f, bb, 2*DIM, DIM, nullptr, nullptr, 0.f, 0, 0, qkv + so);
        tcgS(qkv + so, qkv + Q2 + so,
             SD, HDIM, SD, HDIM, 8*SS, SS, NH, NB*NH,
             0.125f, sc);
        tcgT<true>(sc, qkv + 2*Q2 + so, nullptr,
                   SEQ, HDIM, SEQ, SEQ, DIM, DIM,
                   8*SS, SS, SD, HDIM, SD, HDIM, NH, NB*NH,
                   1.f, nullptr, 0,0, nullptr, nullptr, 0.f, 0, 0, ctx);
        tcgT<true>(ctx, Wh + 3*W, ppt, ROWS, DIM, DIM, DIM, DIM, DIM,
                   0,0,0,0,0,0, 1, 1, 1.f, bb + 3*DIM, 0,0, nullptr, nullptr, 0.f, 0, 0, nullptr);
        ln512_k<<<ROWS, 256>>>(ppt, pav + so, pav + so, lg, lb, nullptr, nullptr,
                               av + so, 512, 0, 0, ROWS);
    };

    auto selfattn = [&](const hf* Wh, const float* bb,
                        const float* lgA, const float* lbA, const float* lgV, const float* lbV) {
        tcgT<true>(av, Wh, nullptr, ROWS, DIM, DIM, DIM, DIM, DIM,
                   RD, 0, 4*W, W, RD, Q2, 3, 6,
                   1.f, bb, 4*DIM, DIM, nullptr, nullptr, 0.f, 0, 0, qkv);
        tcgS(qkv, qkv + Q2,
             SD, HDIM, SD, HDIM, 8*SS, SS, NH, 2*NB*NH,
             0.125f, sc);
        tcgT<true>(sc, qkv + 2*Q2, nullptr,
                   SEQ, HDIM, SEQ, SEQ, DIM, DIM,
                   8*SS, SS, SD, HDIM, SD, HDIM, NH, 2*NB*NH,
                   1.f, nullptr, 0,0, nullptr, nullptr, 0.f, 0, 0, ctx);
        tcgT<true>(ctx, Wh + 3*W, ppt, ROWS, DIM, DIM, DIM, DIM, DIM,
                   RD, 0, 4*W, 0, RD, 0, 1, 2,
                   1.f, bb + 3*DIM, 4*DIM, 0, nullptr, nullptr, 0.f, 0, 0, nullptr);
        ln512_k<<<2*ROWS, 256>>>(ppt, pav, pav, lgA, lbA, lgV, lbV,
                                 av, 512, 0, RD, ROWS);
    };

    auto ffn2 = [&](int l, const float* lgA, const float* lbA, const float* lgV, const float* lbV,
                    bool last) {
        const hf* w1 = f1w + (long long)l * 2 * 512 * 2048;
        const hf* w2 = f2w + (long long)l * 2 * 2048 * 512;
        tcgT<true>(av, w1, nullptr, ROWS, 4*DIM, DIM, DIM, 4*DIM, 4*DIM,
                   RD, 0, (long long)512*2048, 0, (long long)ROWS*2048, 0, 1, 2,
                   1.f, ffn_b1 + (long long)l*2*2048, 2048, 0, nullptr, nullptr, 0.f, 0, 1, hh);
        tcgT<true>(hh, w2, ppt, ROWS, DIM, 4*DIM, 4*DIM, DIM, DIM,
                   (long long)ROWS*2048, 0, (long long)2048*512, 0, RD, 0, 1, 2,
                   1.f, ffn_b2 + (long long)l*2*512, 512, 0, nullptr, nullptr, 0.f, 0, 0, nullptr);
        if (!last)
            ln512_k<<<2*ROWS, 256>>>(ppt, pav, pav, lgA, lbA, lgV, lbV,
                                     av, 512, 0, RD, ROWS);
        else
            ln512_k<<<2*ROWS, 256>>>(ppt, pav, pav, lgA, lbA, lgV, lbV,
                                     cat, 1024, 0, 512, ROWS);
    };

    for (int l = 0; l < NLAYER; l++) {
        const hf* caw0 = caw + (long long)((l*2+0)*4) * W;
        const hf* caw1 = caw + (long long)((l*2+1)*4) * W;
        const hf* saww = saw + (long long)((l*2)*4) * W;
        const float* cab0 = ca_b + (long long)((l*2+0)*4) * DIM;
        const float* cab1 = ca_b + (long long)((l*2+1)*4) * DIM;
        const float* sab  = sa_b + (long long)((l*2)*4) * DIM;
        const float* lg = ln_g + (long long)l * 6 * DIM;
        const float* lb = ln_b + (long long)l * 6 * DIM;
        bool last = (l == NLAYER - 1);

        cross(0, caw0, cab0, lg + 0*DIM, lb + 0*DIM);
        cross(1, caw1, cab1, lg + 3*DIM, lb + 3*DIM);
        selfattn(saww, sab, lg + 1*DIM, lb + 1*DIM, lg + 4*DIM, lb + 4*DIM);
        ffn2(l, lg + 2*DIM, lb + 2*DIM, lg + 5*DIM, lb + 5*DIM, last);
    }

    // ---- fused head ----
    tcgT<true>(cat, oww, ppt, ROWS, DIM, 1024, 1024, DIM, DIM,
               0,0,0,0,0,0, 1, 1, 1.f, out_b, 0,0, nullptr, nullptr, 0.f, 0, 0, nullptr);
    ln512_k<<<ROWS, 256>>>(ppt, nullptr, out, fln_g, fln_b, nullptr, nullptr,
                           nullptr, 512, 0, 0, ROWS);
}

// round 16
// speedup vs baseline: 1.5750x; 1.5750x over previous
#include <cuda_runtime.h>
#include <cuda_fp16.h>
#include <math.h>
#include <stdint.h>

#define NB 8
#define SEQ 256
#define DIM 512
#define NH 8
#define HDIM 64
#define NLAYER 4
#define ROWS (NB*SEQ)
#define RD (ROWS*DIM)
#define NEGV -1e30f

typedef __half hf;
typedef __half2 hf2;

// ---------------- static scratch ----------------
__device__ float g_av [2*RD];
__device__ float g_vo [RD];
__device__ float g_qk [2*RD];
__device__ float g_pt [2*RD];
__device__ float g_sim[NB*SEQ*SEQ];

__device__ hf m_aud[RD];
__device__ hf m_vid[ROWS*256];
__device__ hf m_av [3*RD];
__device__ hf m_qk [2*RD];
__device__ hf m_qkv[6*RD];
__device__ hf m_ctx[2*RD];
__device__ hf m_h  [2*ROWS*2048];
__device__ hf m_sim[NB*SEQ*SEQ];
__device__ hf m_cat[ROWS*1024];

// fp16 weights, NATIVE [K][N] layout
__device__ hf c_ap[512*512];
__device__ hf c_vp[256*512];
__device__ hf c_dtw[512*512];
__device__ hf c_ca[32*512*512];
__device__ hf c_sa[32*512*512];
__device__ hf c_f1[8*512*2048];
__device__ hf c_f2[8*2048*512];
__device__ hf c_o[1024*512];

// ---------------- PTX helpers ----------------
__device__ __forceinline__ uint32_t smem_u32(const void* p) {
    return (uint32_t)__cvta_generic_to_shared(p);
}
__device__ __forceinline__ void cp16(uint32_t so, const void* g) {
    asm volatile("cp.async.cg.shared.global [%0], [%1], 16;" :: "r"(so), "l"(g));
}
__device__ __forceinline__ void ldm4(uint32_t* r, uint32_t addr) {
    asm volatile("ldmatrix.sync.aligned.m8n8.x4.shared.b16 {%0,%1,%2,%3}, [%4];"
        : "=r"(r[0]), "=r"(r[1]), "=r"(r[2]), "=r"(r[3]) : "r"(addr));
}
__device__ __forceinline__ void ldm4t(uint32_t* r, uint32_t addr) {
    asm volatile("ldmatrix.sync.aligned.m8n8.x4.trans.shared.b16 {%0,%1,%2,%3}, [%4];"
        : "=r"(r[0]), "=r"(r[1]), "=r"(r[2]), "=r"(r[3]) : "r"(addr));
}
__device__ __forceinline__ void mma16816(float* d, const uint32_t* a, const uint32_t* b) {
    asm volatile(
        "mma.sync.aligned.m16n8k16.row.col.f32.f16.f16.f32 "
        "{%0,%1,%2,%3}, {%4,%5,%6,%7}, {%8,%9}, {%0,%1,%2,%3};"
        : "+f"(d[0]), "+f"(d[1]), "+f"(d[2]), "+f"(d[3])
        : "r"(a[0]), "r"(a[1]), "r"(a[2]), "r"(a[3]), "r"(b[0]), "r"(b[1]));
}

// ---------------- HMMA GEMM (R14 config: 32-K stages) ----------------
template<int BM, int BN, int NWM, int NWN, bool TRB, int NST>
__global__ void __launch_bounds__(NWM*NWN*32, (NWM*NWN*32 <= 128) ? 3 : 2)
mma_gemm(const hf* __restrict__ A_, const hf* __restrict__ B_,
         float* __restrict__ C,
         int K, int lda, int ldb, int ldc,
         long long sAo, long long sAi, long long sBo, long long sBi,
         long long sCo, long long sCi, int inner,
         float alpha, const float* __restrict__ bias, long long sBO, long long sBI,
         const float* __restrict__ bias2,
         const float* __restrict__ resid, float rscale, int beta, int act,
         hf* outh)
{
    constexpr int TH = NWM * NWN * 32;
    constexpr int WM = BM / NWM;
    constexpr int MF = WM / 16;
    constexpr int WN = BN / NWN;
    constexpr int NF = WN / 8;
    constexpr int ACH = BM * 4;
    constexpr int BCH = BN * 4;
    constexpr int CPR = BN / 8;
    constexpr int STAGE = (BM + BN) * 64;

    extern __shared__ char smem[];
    uint32_t sb = smem_u32(smem);

    int z = blockIdx.z, zo = z / inner, zi = z - zo * inner;
    A_ += zo * sAo + zi * sAi;
    B_ += zo * sBo + zi * sBi;
    long long coff = zo * sCo + zi * sCi;
    if (C) C += coff;
    if (resid) resid += coff;
    if (outh) outh += coff;
    if (bias) bias += zo * sBO + zi * sBI;

    int tid = threadIdx.x, wid = tid >> 5, lane = tid & 31;
    int wm = wid % NWM, wn = wid / NWM;
    int row0 = blockIdx.y * BM, col0 = blockIdx.x * BN;

    auto loadStage = [&](int k0, int st) {
        uint32_t sbase = sb + st * STAGE;
#pragma unroll
        for (int idx = tid; idx < ACH; idx += TH) {
            int r = idx >> 2, c = idx & 3;
            int cs = c ^ ((r >> 1) & 3);
            uint32_t so = sbase + (uint32_t)(r * 4 + cs) * 16;
            long long g = (long long)(row0 + r) * lda + k0 + c * 8;
            cp16(so, A_ + g);
        }
        if (!TRB) {
#pragma unroll
            for (int idx = tid; idx < BCH; idx += TH) {
                int r = idx >> 2, c = idx & 3;
                int cs = c ^ ((r >> 1) & 3);
                uint32_t so = sbase + BM * 64 + (uint32_t)(r * 4 + cs) * 16;
                long long g = (long long)(col0 + r) * ldb + k0 + c * 8;
                cp16(so, B_ + g);
            }
        } else {
#pragma unroll
            for (int idx = tid; idx < BCH; idx += TH) {
                int r = idx / CPR, c = idx % CPR;
                int cs = c ^ (r & 7);
                uint32_t so = sbase + BM * 64 + (uint32_t)(r * CPR + cs) * 16;
                long long g = (long long)(k0 + r) * ldb + col0 + c * 8;
                cp16(so, B_ + g);
            }
        }
        asm volatile("cp.async.commit_group;");
    };

    float acc[MF][NF][4];
#pragma unroll
    for (int i = 0; i < MF; i++)
#pragma unroll
        for (int j = 0; j < NF; j++)
#pragma unroll
            for (int q = 0; q < 4; q++) acc[i][j][q] = 0.f;

    int nch = K / 32;
#pragma unroll
    for (int p = 0; p < NST - 1; p++)
        if (p < nch) loadStage(p * 32, p);

    for (int s = 0; s < nch; s++) {
        int rem = nch - 1 - s;
        if (NST == 2) {
            asm volatile("cp.async.wait_group 0;");
        } else if (NST == 3) {
            if (rem >= 1) { asm volatile("cp.async.wait_group 1;"); }
            else          { asm volatile("cp.async.wait_group 0;"); }
        } else {
            if (rem >= 2)      { asm volatile("cp.async.wait_group 2;"); }
            else if (rem == 1) { asm volatile("cp.async.wait_group 1;"); }
            else               { asm volatile("cp.async.wait_group 0;"); }
        }
        __syncthreads();
        if (s + NST - 1 < nch) loadStage((s + NST - 1) * 32, (s + NST - 1) % NST);
        uint32_t sbase = sb + (s % NST) * STAGE;
#pragma unroll
        for (int ks = 0; ks < 2; ks++) {
            uint32_t ah[MF][4];
#pragma unroll
            for (int mf = 0; mf < MF; mf++) {
                int row = wm * WM + mf * 16 + (lane & 15);
                int c = ks * 2 + (lane >> 4);
                int cs = c ^ ((row >> 1) & 3);
                uint32_t ad = sbase + (uint32_t)(row * 4 + cs) * 16;
                ldm4(ah[mf], ad);
            }
            uint32_t bh[NF][2];
            if (!TRB) {
#pragma unroll
                for (int nf = 0; nf < NF; nf += 2) {
                    int rown = wn * WN + nf * 8 + (lane >> 4) * 8 + (lane & 7);
                    int c = ks * 2 + ((lane >> 3) & 1);
                    int cs = c ^ ((rown >> 1) & 3);
                    uint32_t bd = sbase + BM * 64 + (uint32_t)(rown * 4 + cs) * 16;
                    uint32_t t[4];
                    ldm4(t, bd);
                    bh[nf][0] = t[0]; bh[nf][1] = t[1]; bh[nf+1][0] = t[2]; bh[nf+1][1] = t[3];
                }
            } else {
#pragma unroll
                for (int nf = 0; nf < NF; nf += 2) {
                    int n0 = wn * WN + nf * 8;
                    int k = ks * 16 + (lane & 7) + ((lane >> 3) & 1) * 8;
                    int c = (n0 >> 3) + (lane >> 4);
                    int cs = c ^ (k & 7);
                    uint32_t bd = sbase + BM * 64 + (uint32_t)(k * CPR + cs) * 16;
                    uint32_t t[4];
                    ldm4t(t, bd);
                    bh[nf][0] = t[0]; bh[nf][1] = t[1]; bh[nf+1][0] = t[2]; bh[nf+1][1] = t[3];
                }
            }
#pragma unroll
            for (int mf = 0; mf < MF; mf++)
#pragma unroll
                for (int nf = 0; nf < NF; nf++)
                    mma16816(acc[mf][nf], ah[mf], bh[nf]);
        }
    }

    auto epi2 = [&](int r, int c, float v0, float v1) {
        long long off = (long long)r * ldc + c;
        v0 *= alpha; v1 *= alpha;
        if (bias)  { float2 b2 = *(const float2*)&bias[c];  v0 += b2.x; v1 += b2.y; }
        if (bias2) { float2 b2 = *(const float2*)&bias2[c]; v0 += b2.x; v1 += b2.y; }
        if (beta)  { float2 c2 = *(const float2*)&C[off];   v0 += c2.x; v1 += c2.y; }
        if (resid) { float2 r2 = *(const float2*)&resid[off]; v0 += rscale * r2.x; v1 += rscale * r2.y; }
        if (act) {
            v0 = 0.5f * v0 * (1.f + erff(v0 * 0.70710678118654752f));
            v1 = 0.5f * v1 * (1.f + erff(v1 * 0.70710678118654752f));
        }
        if (C) *(float2*)&C[off] = make_float2(v0, v1);
        if (outh)
            *(hf2*)&outh[off] = hf2(__float2half_rn(v0), __float2half_rn(v1));
    };
#pragma unroll
    for (int mf = 0; mf < MF; mf++) {
        int r0 = row0 + wm * WM + mf * 16 + (lane >> 2);
#pragma unroll
        for (int nf = 0; nf < NF; nf++) {
            int c = col0 + wn * WN + nf * 8 + (lane & 3) * 2;
            epi2(r0,     c, acc[mf][nf][0], acc[mf][nf][1]);
            epi2(r0 + 8, c, acc[mf][nf][2], acc[mf][nf][3]);
        }
    }
}

// ---------------- fused flash attention: ctx = softmax(alpha*Q@K^T) @ V ----------------
// Grid: (4 q-tiles, heads). Per head: Q/K/V [256][64] slices with row stride DIM.
// smem: [0,8K) Qs (A-layout, 2 subs) | [8K,40K) Ks (B-layout, 2 subs of 16K)
//       Ps aliases [0,32K) after phase 1 | [40K,72K) Vs (TRB layout, 8 subs of 4K)
__global__ void __launch_bounds__(256, 2)
fattn_k(const hf* __restrict__ Q_, const hf* __restrict__ Kp, const hf* __restrict__ Vp,
        long long sAo, long long sAi, long long sCo, long long sCi, int inner,
        float alpha, hf* __restrict__ ctxo)
{
    extern __shared__ char smem[];
    uint32_t sb = smem_u32(smem);
    const uint32_t Qs = sb, Ks = sb + 8192, Ps = sb, Vs = sb + 40960;
    __shared__ float sred[64][4];

    int z = blockIdx.y, zo = z / inner, zi = z - zo * inner;
    long long off = zo * sAo + zi * sAi;
    const hf* Q  = Q_ + off;
    const hf* Kk = Kp + off;
    const hf* V  = Vp + off;
    hf* ctx = ctxo + zo * sCo + zi * sCi;

    int tid = threadIdx.x, wid = tid >> 5, lane = tid & 31;
    int wm = wid % 2, wn = wid / 2;       // 2 x 4 warps
    int row0 = blockIdx.x * 64;

    // ---- loads: Q + K (group 1), V (group 2) ----
#pragma unroll
    for (int sub = 0; sub < 2; sub++) {
        {
            int idx = tid;   // 256 chunks exactly
            int r = idx >> 2, c = idx & 3;
            int cs = c ^ ((r >> 1) & 3);
            cp16(Qs + sub * 4096 + (uint32_t)(r * 4 + cs) * 16,
                 Q + (long long)(row0 + r) * DIM + sub * 32 + c * 8);
        }
#pragma unroll
        for (int idx = tid; idx < 1024; idx += 256) {
            int r = idx >> 2, c = idx & 3;
            int cs = c ^ ((r >> 1) & 3);
            cp16(Ks + sub * 16384 + (uint32_t)(r * 4 + cs) * 16,
                 Kk + (long long)r * DIM + sub * 32 + c * 8);
        }
    }
    asm volatile("cp.async.commit_group;");
#pragma unroll
    for (int sub = 0; sub < 8; sub++) {
        int idx = tid;       // 32 k-rows x 8 chunks = 256 exactly
        int r = idx >> 3, c = idx & 7;
        int cs = c ^ (r & 7);
        cp16(Vs + sub * 4096 + (uint32_t)(r * 8 + cs) * 16,
             V + (long long)(sub * 32 + r) * DIM + c * 8);
    }
    asm volatile("cp.async.commit_group;");

    // ---- phase 1: S = Q @ K^T  (BM=64, BN=256, MF=2, NF=8) ----
    float acc[2][8][4];
#pragma unroll
    for (int i = 0; i < 2; i++)
#pragma unroll
        for (int j = 0; j < 8; j++)
#pragma unroll
            for (int q = 0; q < 4; q++) acc[i][j][q] = 0.f;

    asm volatile("cp.async.wait_group 1;");
    __syncthreads();
#pragma unroll
    for (int sub = 0; sub < 2; sub++)
#pragma unroll
    for (int kk = 0; kk < 2; kk++) {
        uint32_t ah[2][4];
#pragma unroll
        for (int mf = 0; mf < 2; mf++) {
            int row = wm * 32 + mf * 16 + (lane & 15);
            int c = kk * 2 + (lane >> 4);
            int cs = c ^ ((row >> 1) & 3);
            ldm4(ah[mf], Qs + sub * 4096 + (uint32_t)(row * 4 + cs) * 16);
        }
        uint32_t bh[8][2];
#pragma unroll
        for (int nf = 0; nf < 8; nf += 2) {
            int rown = wn * 64 + nf * 8 + (lane >> 4) * 8 + (lane & 7);
            int c = kk * 2 + ((lane >> 3) & 1);
            int cs = c ^ ((rown >> 1) & 3);
            uint32_t t[4];
            ldm4(t, Ks + sub * 16384 + (uint32_t)(rown * 4 + cs) * 16);
            bh[nf][0] = t[0]; bh[nf][1] = t[1]; bh[nf+1][0] = t[2]; bh[nf+1][1] = t[3];
        }
#pragma unroll
        for (int mf = 0; mf < 2; mf++)
#pragma unroll
            for (int nf = 0; nf < 8; nf++)
                mma16816(acc[mf][nf], ah[mf], bh[nf]);
    }

    // ---- softmax over 256-wide rows ----
    float rmax[2][2], rsum[2][2];
    __syncthreads();
#pragma unroll
    for (int mf = 0; mf < 2; mf++)
#pragma unroll
        for (int h = 0; h < 2; h++) {
            float m = NEGV;
#pragma unroll
            for (int nf = 0; nf < 8; nf++)
                m = fmaxf(m, fmaxf(acc[mf][nf][h*2], acc[mf][nf][h*2+1]));
            m = fmaxf(m, __shfl_xor_sync(0xffffffffu, m, 1));
            m = fmaxf(m, __shfl_xor_sync(0xffffffffu, m, 2));
            int rl = wm * 32 + mf * 16 + (lane >> 2) + h * 8;
            if ((lane & 3) == 0) sred[rl][wn] = m;
        }
    __syncthreads();
#pragma unroll
    for (int mf = 0; mf < 2; mf++)
#pragma unroll
        for (int h = 0; h < 2; h++) {
            int rl = wm * 32 + mf * 16 + (lane >> 2) + h * 8;
            float m = sred[rl][0];
#pragma unroll
            for (int w = 1; w < 4; w++) m = fmaxf(m, sred[rl][w]);
            rmax[mf][h] = m;
        }
    __syncthreads();
#pragma unroll
    for (int mf = 0; mf < 2; mf++)
#pragma unroll
        for (int h = 0; h < 2; h++) {
            float ssum = 0.f;
#pragma unroll
            for (int nf = 0; nf < 8; nf++) {
                float e0 = expf(acc[mf][nf][h*2]   * alpha - rmax[mf][h] * alpha);
                float e1 = expf(acc[mf][nf][h*2+1] * alpha - rmax[mf][h] * alpha);
                acc[mf][nf][h*2] = e0; acc[mf][nf][h*2+1] = e1;
                ssum += e0 + e1;
            }
            ssum += __shfl_xor_sync(0xffffffffu, ssum, 1);
            ssum += __shfl_xor_sync(0xffffffffu, ssum, 2);
            int rl = wm * 32 + mf * 16 + (lane >> 2) + h * 8;
            if ((lane & 3) == 0) sred[rl][wn] = ssum;
        }
    __syncthreads();
#pragma unroll
    for (int mf = 0; mf < 2; mf++)
#pragma unroll
        for (int h = 0; h < 2; h++) {
            int rl = wm * 32 + mf * 16 + (lane >> 2) + h * 8;
            float t = 0.f;
#pragma unroll
            for (int w = 0; w < 4; w++) t += sred[rl][w];
            rsum[mf][h] = 1.f / t;
        }

    // ---- write P (fp16) to smem in A-operand layout (aliases Q/K region) ----
    // all Q/K reads completed before the barriers above
#pragma unroll
    for (int mf = 0; mf < 2; mf++)
#pragma unroll
        for (int h = 0; h < 2; h++) {
            int rl = wm * 32 + mf * 16 + (lane >> 2) + h * 8;
#pragma unroll
            for (int nf = 0; nf < 8; nf++) {
                int k = wn * 64 + nf * 8 + (lane & 3) * 2;
                float v0 = acc[mf][nf][h*2]   * rsum[mf][h];
                float v1 = acc[mf][nf][h*2+1] * rsum[mf][h];
                int sub = k >> 5;
                int c = (k & 31) >> 3;
                int cs = c ^ ((rl >> 1) & 3);
                uint32_t bo = (uint32_t)(sub * 4096 + (rl * 4 + cs) * 16 + (k & 7) * 2);
                *(hf2*)(smem + bo) = hf2(__float2half_rn(v0), __float2half_rn(v1));
            }
        }
    asm volatile("cp.async.wait_group 0;");
    __syncthreads();

    // ---- phase 2: ctx = P @ V  (BM=64, BN=64, MF=2, NF=2, WN=16) ----
    float acc2[2][2][4];
#pragma unroll
    for (int i = 0; i < 2; i++)
#pragma unroll
        for (int j = 0; j < 2; j++)
#pragma unroll
            for (int q = 0; q < 4; q++) acc2[i][j][q] = 0.f;

#pragma unroll
    for (int sub = 0; sub < 8; sub++)
#pragma unroll
    for (int kk = 0; kk < 2; kk++) {
        uint32_t ah[2][4];
#pragma unroll
        for (int mf = 0; mf < 2; mf++) {
            int row = wm * 32 + mf * 16 + (lane & 15);
            int c = kk * 2 + (lane >> 4);
            int cs = c ^ ((row >> 1) & 3);
            ldm4(ah[mf], Ps + sub * 4096 + (uint32_t)(row * 4 + cs) * 16);
        }
        uint32_t bh[2][2];
        {
            int n0 = wn * 16;
            int k = kk * 16 + (lane & 7) + ((lane >> 3) & 1) * 8;
            int c = (n0 >> 3) + (lane >> 4);
            int cs = c ^ (k & 7);
            uint32_t t[4];
            ldm4t(t, Vs + sub * 4096 + (uint32_t)(k * 8 + cs) * 16);
            bh[0][0] = t[0]; bh[0][1] = t[1]; bh[1][0] = t[2]; bh[1][1] = t[3];
        }
#pragma unroll
        for (int mf = 0; mf < 2; mf++)
#pragma unroll
            for (int nf = 0; nf < 2; nf++)
                mma16816(acc2[mf][nf], ah[mf], bh[nf]);
    }

    // ---- epilogue: ctx fp16 mirrors ----
#pragma unroll
    for (int mf = 0; mf < 2; mf++) {
        int r0 = row0 + wm * 32 + mf * 16 + (lane >> 2);
#pragma unroll
        for (int nf = 0; nf < 2; nf++) {
            int c = wn * 16 + nf * 8 + (lane & 3) * 2;
            long long o0 = (long long)r0 * DIM + c;
            long long o1 = (long long)(r0 + 8) * DIM + c;
            *(hf2*)&ctx[o0] = hf2(__float2half_rn(acc2[mf][nf][0]), __float2half_rn(acc2[mf][nf][1]));
            *(hf2*)&ctx[o1] = hf2(__float2half_rn(acc2[mf][nf][2]), __float2half_rn(acc2[mf][nf][3]));
        }
    }
}

// ---------------- mega convert ----------------
#define NSEG 10
struct CvtArgs {
    const float* src[NSEG];
    hf* dh[NSEG];
    long long cum[NSEG + 1];
};
__global__ void cvtall_k(CvtArgs a)
{
    long long i = ((long long)blockIdx.x * 256 + threadIdx.x) * 4;
    if (i >= a.cum[NSEG]) return;
    int s = 0;
#pragma unroll
    for (int q = 0; q < NSEG; q++) if (i >= a.cum[q + 1]) s = q + 1;
    long long o = i - a.cum[s];
    float4 v = *(const float4*)(a.src[s] + o);
    *(hf2*)(a.dh[s] + o)     = hf2(__float2half_rn(v.x), __float2half_rn(v.y));
    *(hf2*)(a.dh[s] + o + 2) = hf2(__float2half_rn(v.z), __float2half_rn(v.w));
}

// ---------------- softmax 256-wide -> fp16 (sim path only) ----------------
__global__ void softmax256_k(const float* __restrict__ x, hf* __restrict__ oh)
{
    __shared__ float red[8];
    __shared__ float bc[2];
    int t = threadIdx.x;
    const float* p = x + (long long)blockIdx.x * 256;
    float v = p[t];
    float m = v;
#pragma unroll
    for (int o = 16; o; o >>= 1) m = fmaxf(m, __shfl_xor_sync(0xffffffffu, m, o));
    if ((t & 31) == 0) red[t >> 5] = m;
    __syncthreads();
    if (t == 0) { float mm = red[0]; for (int i = 1; i < 8; i++) mm = fmaxf(mm, red[i]); bc[0] = mm; }
    __syncthreads();
    float e = expf(v - bc[0]);
    float s = e;
#pragma unroll
    for (int o = 16; o; o >>= 1) s += __shfl_xor_sync(0xffffffffu, s, o);
    if ((t & 31) == 0) red[t >> 5] = s;
    __syncthreads();
    if (t == 0) { float tt = 0.f; for (int i = 0; i < 8; i++) tt += red[i]; bc[1] = 1.f / tt; }
    __syncthreads();
    oh[(long long)blockIdx.x * 256 + t] = __float2half_rn(e * bc[1]);
}

// ---------------- LayerNorm 512 wide ----------------
__global__ void ln512_k(const float* __restrict__ x, const float* r, float* y,
                        const float* __restrict__ g1, const float* __restrict__ b1,
                        const float* g2, const float* b2,
                        hf* oh, int ldm, int moff0, int moff1, int rps)
{
    __shared__ float red[8];
    __shared__ float bc;
    long long row = blockIdx.x;
    int t = threadIdx.x;
    bool s2 = (g2 != nullptr) && (row >= rps);
    const float* g = s2 ? g2 : g1;
    const float* bb = s2 ? b2 : b1;
    const float* px = x + row * 512;
    float v0 = px[t], v1 = px[t + 256];
    if (r) { const float* pr = r + row * 512; v0 += pr[t]; v1 += pr[t + 256]; }
    float s = v0 + v1;
#pragma unroll
    for (int o = 16; o; o >>= 1) s += __shfl_xor_sync(0xffffffffu, s, o);
    if ((t & 31) == 0) red[t >> 5] = s;
    __syncthreads();
    if (t == 0) { float tt = 0.f; for (int i = 0; i < 8; i++) tt += red[i]; bc = tt * (1.f / 512.f); }
    __syncthreads();
    float mean = bc;
    float d0 = v0 - mean, d1 = v1 - mean;
    float q = d0 * d0 + d1 * d1;
#pragma unroll
    for (int o = 16; o; o >>= 1) q += __shfl_xor_sync(0xffffffffu, q, o);
    if ((t & 31) == 0) red[t >> 5] = q;
    __syncthreads();
    if (t == 0) { float tt = 0.f; for (int i = 0; i < 8; i++) tt += red[i]; bc = tt * (1.f / 512.f); }
    __syncthreads();
    float inv = rsqrtf(bc + 1e-5f);
    float y0 = d0 * inv * g[t]       + bb[t];
    float y1 = d1 * inv * g[t + 256] + bb[t + 256];
    float* py = y + row * 512;
    py[t] = y0;  py[t + 256] = y1;
    if (oh) {
        long long mo = s2 ? ((row - rps) * (long long)ldm + moff1)
                          : (row * (long long)ldm + moff0);
        oh[mo + t] = __float2half_rn(y0);
        oh[mo + t + 256] = __float2half_rn(y1);
    }
}

// ---------------- L2 normalize ----------------
__global__ void l2n_k(float* x, hf* oh)
{
    __shared__ float red[8];
    __shared__ float bc;
    long long row = blockIdx.x;
    int t = threadIdx.x;
    float* p = x + row * 512;
    float v0 = p[t], v1 = p[t + 256];
    float q = v0 * v0 + v1 * v1;
#pragma unroll
    for (int o = 16; o; o >>= 1) q += __shfl_xor_sync(0xffffffffu, q, o);
    if ((t & 31) == 0) red[t >> 5] = q;
    __syncthreads();
    if (t == 0) { float tt = 0.f; for (int i = 0; i < 8; i++) tt += red[i];
                  bc = 1.f / fmaxf(sqrtf(tt), 1e-12f); }
    __syncthreads();
    v0 *= bc; v1 *= bc;
    p[t] = v0; p[t + 256] = v1;
    oh[row * 512 + t] = __float2half_rn(v0);
    oh[row * 512 + t + 256] = __float2half_rn(v1);
}

// ---------------- DTW wavefront DP ----------------
__global__ void dtw_k(const float* __restrict__ sim, float* score)
{
    __shared__ float buf[3][SEQ + 1];
    int b = blockIdx.x;
    const float* S = sim + (long long)b * SEQ * SEQ;
    int t = threadIdx.x;
    float *dm2 = buf[0], *dm1 = buf[1], *dc = buf[2];
    if (t == 0) { buf[0][0] = 0.f; buf[1][0] = NEGV; buf[1][1] = NEGV; }
    __syncthreads();
    for (int td = 2; td <= 2 * SEQ; td++) {
        int i = t + 1;
        int j = td - i;
        float val = 0.f;
        bool active = (j >= 1 && j <= SEQ);
        if (active) {
            float dg = dm2[i - 1];
            float up = dm1[i - 1];
            float lf = dm1[i];
            val = S[(i - 1) * SEQ + (j - 1)] + fmaxf(dg, fmaxf(up, lf));
            dc[i] = val;
        }
        if (t == 0 && td <= SEQ) { dc[0] = NEGV; dc[td] = NEGV; }
        if (td == 2 * SEQ && i == SEQ) score[b] = val;
        __syncthreads();
        float* tmp = dm2; dm2 = dm1; dm1 = dc; dc = tmp;
    }
}

// ---------------- launch helpers ----------------
template<bool TRB>
static void tcgT(const hf* A, const hf* B,
                 float* C, int M, int N, int K, int lda, int ldb, int ldc,
                 long long sAo, long long sAi, long long sBo, long long sBi,
                 long long sCo, long long sCi, int inner, int batch,
                 float alpha, const float* bias, long long sBO, long long sBI,
                 const float* bias2,
                 const float* resid, float rs, int beta, int act,
                 hf* outh)
{
    static const int cand[3][2] = { {128,128}, {64,128}, {64,64} };
    int chosen = -1, best = -1;
    long long bestC = -1;
    for (int i = 0; i < 3; i++) {
        int bm = cand[i][0], bn = cand[i][1];
        if (M % bm || N % bn) continue;
        long long c = (long long)(M / bm) * (N / bn) * batch;
        if (c >= 240) { chosen = i; break; }
        if (c > bestC) { bestC = c; best = i; }
    }
    if (chosen < 0) chosen = best;
    if (chosen == 0) {
        constexpr int SM = 3 * (128 + 128) * 64;
        cudaFuncSetAttribute(mma_gemm<128,128,4,2,TRB,3>, cudaFuncAttributeMaxDynamicSharedMemorySize, SM);
        mma_gemm<128,128,4,2,TRB,3><<<dim3(N/128, M/128, batch), 256, SM>>>(
            A, B, C, K, lda, ldb, ldc, sAo, sAi, sBo, sBi, sCo, sCi, inner,
            alpha, bias, sBO, sBI, bias2, resid, rs, beta, act, outh);
    } else if (chosen == 1) {
        constexpr int SM = 4 * (64 + 128) * 64;
        cudaFuncSetAttribute(mma_gemm<64,128,2,2,TRB,4>, cudaFuncAttributeMaxDynamicSharedMemorySize, SM);
        mma_gemm<64,128,2,2,TRB,4><<<dim3(N/128, M/64, batch), 128, SM>>>(
            A, B, C, K, lda, ldb, ldc, sAo, sAi, sBo, sBi, sCo, sCi, inner,
            alpha, bias, sBO, sBI, bias2, resid, rs, beta, act, outh);
    } else {
        constexpr int SM = 4 * (64 + 64) * 64;
        cudaFuncSetAttribute(mma_gemm<64,64,2,2,TRB,4>, cudaFuncAttributeMaxDynamicSharedMemorySize, SM);
        mma_gemm<64,64,2,2,TRB,4><<<dim3(N/64, M/64, batch), 128, SM>>>(
            A, B, C, K, lda, ldb, ldc, sAo, sAi, sBo, sBi, sCo, sCi, inner,
            alpha, bias, sBO, sBI, bias2, resid, rs, beta, act, outh);
    }
}

static void fattn(const hf* Q, const hf* K, const hf* V, hf* ctx,
                  long long sAo, long long sAi, long long sCo, long long sCi,
                  int inner, int heads)
{
    constexpr int SM = 73728;
    cudaFuncSetAttribute(fattn_k, cudaFuncAttributeMaxDynamicSharedMemorySize, SM);
    fattn_k<<<dim3(SEQ/64, heads), 256, SM>>>(Q, K, V, sAo, sAi, sCo, sCi, inner, 0.125f, ctx);
}

extern "C" void kernel_launch(void* const* d_in, const int* in_sizes, int n_in,
                              void* d_out, int out_size)
{
    const float* audio  = (const float*)d_in[0];
    const float* video  = (const float*)d_in[1];
    const float* ap_w   = (const float*)d_in[2];
    const float* ap_b   = (const float*)d_in[3];
    const float* vp_w   = (const float*)d_in[4];
    const float* vp_b   = (const float*)d_in[5];
    const float* dtw_w  = (const float*)d_in[6];
    const float* dtw_b  = (const float*)d_in[7];
    const float* mod_emb= (const float*)d_in[8];
    const float* ca_w   = (const float*)d_in[9];
    const float* ca_b   = (const float*)d_in[10];
    const float* sa_w   = (const float*)d_in[11];
    const float* sa_b   = (const float*)d_in[12];
    const float* ln_g   = (const float*)d_in[13];
    const float* ln_b   = (const float*)d_in[14];
    const float* ffn_w1 = (const float*)d_in[15];
    const float* ffn_b1 = (const float*)d_in[16];
    const float* ffn_w2 = (const float*)d_in[17];
    const float* ffn_b2 = (const float*)d_in[18];
    const float* out_w  = (const float*)d_in[19];
    const float* out_b  = (const float*)d_in[20];
    const float* fln_g  = (const float*)d_in[21];
    const float* fln_b  = (const float*)d_in[22];

    float *pav,*pvo,*pqk,*ppt,*psim;
    cudaGetSymbolAddress((void**)&pav, g_av);
    cudaGetSymbolAddress((void**)&pvo, g_vo);
    cudaGetSymbolAddress((void**)&pqk, g_qk);
    cudaGetSymbolAddress((void**)&ppt, g_pt);
    cudaGetSymbolAddress((void**)&psim,g_sim);

    hf *aud,*vid,*av,*qk,*qkv,*ctx,*hh,*sim,*cat;
    hf *apw,*vpw,*dtww,*caw,*saw,*f1w,*f2w,*oww;
    cudaGetSymbolAddress((void**)&aud, m_aud);
    cudaGetSymbolAddress((void**)&vid, m_vid);
    cudaGetSymbolAddress((void**)&av, m_av);
    cudaGetSymbolAddress((void**)&qk, m_qk);
    cudaGetSymbolAddress((void**)&qkv, m_qkv);
    cudaGetSymbolAddress((void**)&ctx, m_ctx);
    cudaGetSymbolAddress((void**)&hh, m_h);
    cudaGetSymbolAddress((void**)&sim, m_sim);
    cudaGetSymbolAddress((void**)&cat, m_cat);
    cudaGetSymbolAddress((void**)&apw, c_ap);
    cudaGetSymbolAddress((void**)&vpw, c_vp);
    cudaGetSymbolAddress((void**)&dtww, c_dtw);
    cudaGetSymbolAddress((void**)&caw, c_ca);
    cudaGetSymbolAddress((void**)&saw, c_sa);
    cudaGetSymbolAddress((void**)&f1w, c_f1);
    cudaGetSymbolAddress((void**)&f2w, c_f2);
    cudaGetSymbolAddress((void**)&oww, c_o);

    float* out = (float*)d_out;
    float* out_score = out + (out_size - NB);

    const long long SD  = (long long)SEQ * DIM;
    const long long SS  = (long long)SEQ * SEQ;
    const long long W   = (long long)DIM * DIM;
    const long long Q2  = 2LL * RD;

    // ---- ONE convert launch ----
    {
        CvtArgs a;
        const float* srcs[NSEG] = { ap_w, vp_w, dtw_w, ca_w, sa_w, ffn_w1, ffn_w2, out_w, audio, video };
        hf* dhs[NSEG] = { apw, vpw, dtww, caw, saw, f1w, f2w, oww, aud, vid };
        long long ns[NSEG] = { 512*512, 256*512, 512*512, 32ll*512*512, 32ll*512*512,
                               8ll*512*2048, 8ll*2048*512, 1024*512, (long long)RD, (long long)ROWS*256 };
        long long cum = 0;
        for (int i = 0; i < NSEG; i++) {
            a.src[i] = srcs[i]; a.dh[i] = dhs[i];
            a.cum[i] = cum; cum += ns[i];
        }
        a.cum[NSEG] = cum;
        cvtall_k<<<(int)((cum / 4 + 255) / 256), 256>>>(a);
    }

    // ---- projections ----
    tcgT<true>(aud, apw, pav, ROWS, DIM, DIM, DIM, DIM, DIM,
               0,0,0,0,0,0, 1, 1, 1.f, ap_b, 0,0, mod_emb, nullptr, 0.f, 0, 0, av);
    tcgT<true>(vid, vpw, pvo, ROWS, DIM, 256, 256, DIM, DIM,
               0,0,0,0,0,0, 1, 1, 1.f, vp_b, 0,0, mod_emb + DIM, nullptr, 0.f, 0, 0, av + 2*RD);

    // ---- DTW ----
    tcgT<true>(av, dtww, pqk, ROWS, DIM, DIM, DIM, DIM, DIM,
               2*RD, 0, 0, 0, RD, 0, 1, 2,
               1.f, dtw_b, 0,0, nullptr, nullptr, 0.f, 0, 0, qk);
    l2n_k<<<2*ROWS, 256>>>(pqk, qk);
    tcgT<false>(qk, qk + RD, psim, SEQ, SEQ, DIM, DIM, DIM, SEQ,
                SD, 0, SD, 0, SS, 0, 1, NB,
                1.f, nullptr, 0,0, nullptr, nullptr, 0.f, 0, 0, nullptr);
    dtw_k<<<NB, 256>>>(psim, out_score);
    softmax256_k<<<NB*SEQ, 256>>>(psim, sim);
    tcgT<true>(sim, av + 2*RD, pav + RD, SEQ, DIM, SEQ, SEQ, DIM, DIM,
               SS, 0, SD, 0, SD, 0, 1, NB,
               0.5f, nullptr, 0,0, nullptr, pvo, 0.5f, 0, 0, av + RD);

    auto cross = [&](int s, const hf* Wh, const float* bb,
                     const float* lg, const float* lb) {
        long long so = (long long)s * RD;
        long long d  = (1 - 2 * s) * (long long)RD;
        tcgT<true>(av + so, Wh, nullptr, ROWS, DIM, DIM, DIM, DIM, DIM,
                   d, d, 2*W, W, 2*Q2, Q2, 2, 3,
                   1.f, bb, 2*DIM, DIM, nullptr, nullptr, 0.f, 0, 0, qkv + so);
        fattn(qkv + so, qkv + Q2 + so, qkv + 2*Q2 + so, ctx,
              SD, HDIM, SD, HDIM, NH, NB*NH);
        tcgT<true>(ctx, Wh + 3*W, ppt, ROWS, DIM, DIM, DIM, DIM, DIM,
                   0,0,0,0,0,0, 1, 1, 1.f, bb + 3*DIM, 0,0, nullptr, nullptr, 0.f, 0, 0, nullptr);
        ln512_k<<<ROWS, 256>>>(ppt, pav + so, pav + so, lg, lb, nullptr, nullptr,
                               av + so, 512, 0, 0, ROWS);
    };

    auto selfattn = [&](const hf* Wh, const float* bb,
                        const float* lgA, const float* lbA, const float* lgV, const float* lbV) {
        tcgT<true>(av, Wh, nullptr, ROWS, DIM, DIM, DIM, DIM, DIM,
                   RD, 0, 4*W, W, RD, Q2, 3, 6,
                   1.f, bb, 4*DIM, DIM, nullptr, nullptr, 0.f, 0, 0, qkv);
        fattn(qkv, qkv + Q2, qkv + 2*Q2, ctx,
              SD, HDIM, SD, HDIM, NH, 2*NB*NH);
        tcgT<true>(ctx, Wh + 3*W, ppt, ROWS, DIM, DIM, DIM, DIM, DIM,
                   RD, 0, 4*W, 0, RD, 0, 1, 2,
                   1.f, bb + 3*DIM, 4*DIM, 0, nullptr, nullptr, 0.f, 0, 0, nullptr);
        ln512_k<<<2*ROWS, 256>>>(ppt, pav, pav, lgA, lbA, lgV, lbV,
                                 av, 512, 0, RD, ROWS);
    };

    auto ffn2 = [&](int l, const float* lgA, const float* lbA, const float* lgV, const float* lbV,
                    bool last) {
        const hf* w1 = f1w + (long long)l * 2 * 512 * 2048;
        const hf* w2 = f2w + (long long)l * 2 * 2048 * 512;
        tcgT<true>(av, w1, nullptr, ROWS, 4*DIM, DIM, DIM, 4*DIM, 4*DIM,
                   RD, 0, (long long)512*2048, 0, (long long)ROWS*2048, 0, 1, 2,
                   1.f, ffn_b1 + (long long)l*2*2048, 2048, 0, nullptr, nullptr, 0.f, 0, 1, hh);
        tcgT<true>(hh, w2, ppt, ROWS, DIM, 4*DIM, 4*DIM, DIM, DIM,
                   (long long)ROWS*2048, 0, (long long)2048*512, 0, RD, 0, 1, 2,
                   1.f, ffn_b2 + (long long)l*2*512, 512, 0, nullptr, nullptr, 0.f, 0, 0, nullptr);
        if (!last)
            ln512_k<<<2*ROWS, 256>>>(ppt, pav, pav, lgA, lbA, lgV, lbV,
                                     av, 512, 0, RD, ROWS);
        else
            ln512_k<<<2*ROWS, 256>>>(ppt, pav, pav, lgA, lbA, lgV, lbV,
                                     cat, 1024, 0, 512, ROWS);
    };

    for (int l = 0; l < NLAYER; l++) {
        const hf* caw0 = caw + (long long)((l*2+0)*4) * W;
        const hf* caw1 = caw + (long long)((l*2+1)*4) * W;
        const hf* saww = saw + (long long)((l*2)*4) * W;
        const float* cab0 = ca_b + (long long)((l*2+0)*4) * DIM;
        const float* cab1 = ca_b + (long long)((l*2+1)*4) * DIM;
        const float* sab  = sa_b + (long long)((l*2)*4) * DIM;
        const float* lg = ln_g + (long long)l * 6 * DIM;
        const float* lb = ln_b + (long long)l * 6 * DIM;
        bool last = (l == NLAYER - 1);

        cross(0, caw0, cab0, lg + 0*DIM, lb + 0*DIM);
        cross(1, caw1, cab1, lg + 3*DIM, lb + 3*DIM);
        selfattn(saww, sab, lg + 1*DIM, lb + 1*DIM, lg + 4*DIM, lb + 4*DIM);
        ffn2(l, lg + 2*DIM, lb + 2*DIM, lg + 5*DIM, lb + 5*DIM, last);
    }

    // ---- fused head ----
    tcgT<true>(cat, oww, ppt, ROWS, DIM, 1024, 1024, DIM, DIM,
               0,0,0,0,0,0, 1, 1, 1.f, out_b, 0,0, nullptr, nullptr, 0.f, 0, 0, nullptr);
    ln512_k<<<ROWS, 256>>>(ppt, nullptr, out, fln_g, fln_b, nullptr, nullptr,
                           nullptr, 512, 0, 0, ROWS);
}